// round 16
// baseline (speedup 1.0000x reference)
#include <cuda_runtime.h>
#include <math.h>
#include <stdint.h>

// DPLSTMCell row-0, R16: R14 (warm-best 8.67us) + tail shaving.
//  - Outputs paired consecutively: n0=2*bid, n1=2*bid+1 (adjacent weight rows ->
//    same DRAM page on the cold pass).
//  - Biases + c_prev prefetched into registers by the two epilogue lanes at kernel
//    start, removing the dependent-LDG tail after the final barrier.
// Partition (proven R10/R14): warps 0-3 Wih via interleaved LDG.128 (ptxas schedule;
// front-batching regressed R13), warps 4-7 Whh via cp.async.cg. Fast MUFU epilogue.
// No .nc/evict/TMA (warm regressions R5/R7/R12).

#define H 1024
#define D 1024
#define NOUT 512   // blocks; outputs 2*bid and 2*bid+1

__device__ __forceinline__ float warp_reduce(float v) {
    #pragma unroll
    for (int off = 16; off > 0; off >>= 1)
        v += __shfl_xor_sync(0xFFFFFFFFu, v, off);
    return v;
}

__device__ __forceinline__ float fast_tanh(float x) {
    float r;
    asm("tanh.approx.f32 %0, %1;" : "=f"(r) : "f"(x));
    return r;
}
__device__ __forceinline__ float fast_sigmoid(float x) {
    return 0.5f * fast_tanh(0.5f * x) + 0.5f;
}

__global__ __launch_bounds__(256)
void lstm_row0_x2c_kernel(const float* __restrict__ x,
                          const float* __restrict__ h,
                          const float* __restrict__ c_prev,
                          const float* __restrict__ Wih,
                          const float* __restrict__ Whh,
                          const float* __restrict__ bih,
                          const float* __restrict__ bhh,
                          float* __restrict__ out) {
    // async path: 4 gates x 2 outputs x 256 float4 = 32KB
    __shared__ __align__(128) float4 swh[4][2][256];
    __shared__ float sums[2][8];

    const int n0   = 2 * blockIdx.x;
    const int n1   = n0 + 1;
    const int tid  = threadIdx.x;
    const int wid  = tid >> 5;
    const int lane = tid & 31;

    // ---- epilogue prefetch: lanes 0,1 of warp 0 pull biases + c_prev early ----
    float pb0 = 0.f, pb1 = 0.f, pb2 = 0.f, pb3 = 0.f;
    float pc0 = 0.f, pc1 = 0.f, pc2 = 0.f, pc3 = 0.f;
    float pcp = 0.f;
    if (tid < 2) {
        const int n = n0 + tid;
        pb0 = bih[n];          pc0 = bhh[n];
        pb1 = bih[H + n];      pc1 = bhh[H + n];
        pb2 = bih[2 * H + n];  pc2 = bhh[2 * H + n];
        pb3 = bih[3 * H + n];  pc3 = bhh[3 * H + n];
        pcp = c_prev[n];
    }

    float acc0 = 0.0f, acc1 = 0.0f;

    if (wid >= 4) {
        // ---- async path: Whh rows for gate = wid-4, both outputs ----
        const int gate = wid - 4;
        const float* s0 = Whh + (size_t)(gate * H + n0) * D;
        const float* s1 = s0 + D;                     // adjacent row (n1)
        #pragma unroll
        for (int i = 0; i < 8; i++) {
            const int idx = lane + i * 32;
            uint32_t d0 = (uint32_t)__cvta_generic_to_shared(&swh[gate][0][idx]);
            uint32_t d1 = (uint32_t)__cvta_generic_to_shared(&swh[gate][1][idx]);
            asm volatile("cp.async.cg.shared.global [%0], [%1], 16;"
                         :: "r"(d0), "l"(s0 + idx * 4) : "memory");
            asm volatile("cp.async.cg.shared.global [%0], [%1], 16;"
                         :: "r"(d1), "l"(s1 + idx * 4) : "memory");
        }
        asm volatile("cp.async.commit_group;" ::: "memory");

        // Vector h (L1/L2-hot) overlaps the async transfers.
        const float4* __restrict__ v4 = reinterpret_cast<const float4*>(h);
        float4 vr[8];
        #pragma unroll
        for (int i = 0; i < 8; i++)
            vr[i] = v4[lane + i * 32];

        asm volatile("cp.async.wait_group 0;" ::: "memory");
        __syncwarp();

        #pragma unroll
        for (int i = 0; i < 8; i++) {
            const int idx = lane + i * 32;
            const float4 w0 = swh[gate][0][idx];
            const float4 w1 = swh[gate][1][idx];
            acc0 += w0.x * vr[i].x + w0.y * vr[i].y + w0.z * vr[i].z + w0.w * vr[i].w;
            acc1 += w1.x * vr[i].x + w1.y * vr[i].y + w1.z * vr[i].z + w1.w * vr[i].w;
        }
    } else {
        // ---- LDG path: Wih rows for gate = wid, both outputs, interleaved ----
        const int gate = wid;
        const float4* __restrict__ wa = reinterpret_cast<const float4*>(
            Wih + (size_t)(gate * H + n0) * D);
        const float4* __restrict__ wb = wa + D / 4;   // adjacent row (n1)
        const float4* __restrict__ v4 = reinterpret_cast<const float4*>(x);
        #pragma unroll
        for (int i = 0; i < 8; i++) {
            const int idx = lane + i * 32;
            const float4 w0 = wa[idx];
            const float4 w1 = wb[idx];
            const float4 xv = v4[idx];
            acc0 += w0.x * xv.x + w0.y * xv.y + w0.z * xv.z + w0.w * xv.w;
            acc1 += w1.x * xv.x + w1.y * xv.y + w1.z * xv.z + w1.w * xv.w;
        }
    }

    acc0 = warp_reduce(acc0);
    acc1 = warp_reduce(acc1);
    if (lane == 0) {
        sums[0][wid] = acc0;
        sums[1][wid] = acc1;
    }
    __syncthreads();

    // Two epilogues on two lanes of warp 0; biases/c_prev already in registers.
    if (tid < 2) {
        const int o = tid;                 // 0 -> n0, 1 -> n1
        const int n = n0 + o;
        // sums[o][g] = Wih·x for gate g ; sums[o][4+g] = Whh·h for gate g
        float gi = sums[o][0] + sums[o][4] + pb0 + pc0;
        float gf = sums[o][1] + sums[o][5] + pb1 + pc1;
        float gg = sums[o][2] + sums[o][6] + pb2 + pc2;
        float go = sums[o][3] + sums[o][7] + pb3 + pc3;

        float i_t = fast_sigmoid(gi);
        float f_t = fast_sigmoid(gf);
        float g_t = fast_tanh(gg);
        float o_t = fast_sigmoid(go);

        float c_t = f_t * pcp + i_t * g_t;
        out[n] = o_t * fast_tanh(c_t);
    }
}

extern "C" void kernel_launch(void* const* d_in, const int* in_sizes, int n_in,
                              void* d_out, int out_size) {
    const float* x      = (const float*)d_in[0];
    const float* h      = (const float*)d_in[1];
    const float* c_prev = (const float*)d_in[2];
    const float* Wih    = (const float*)d_in[3];
    const float* Whh    = (const float*)d_in[4];
    const float* bih    = (const float*)d_in[5];
    const float* bhh    = (const float*)d_in[6];
    float* out = (float*)d_out;

    lstm_row0_x2c_kernel<<<NOUT, 256>>>(x, h, c_prev, Wih, Whh, bih, bhh, out);
}